// round 13
// baseline (speedup 1.0000x reference)
#include <cuda_runtime.h>
#include <cuda_fp16.h>

// Problem sizes
#define Bn   256
#define Tn   512
#define EMBn 64
#define HSn  512
#define VSn  128

// 8 row-groups (32 batch rows) x 16 col-tiles (32 hidden cols) = 128 CTAs
#define GRID   128
#define NGROUP 8
#define GSIZE  16
#define BLOCKT 256           // 8 warps, 255-reg budget
#define WSC    1616          // combined W plane row stride (u32); 1616%32==16
#define HPS    512           // packed-h row stride in u32 (256 kpairs * 2)
#define RS     544           // recurrence reduction stride (32*17)
#define WS2    264           // FC B plane row stride
#define RS2    1056          // FC reduction stride (32*33)

#define SMEM_U32   (32 * WSC + 5120)      // 56832 u32
#define SMEM_BYTES (SMEM_U32 * 4)         // 227,328 B

typedef unsigned int u32;

// -------- persistent device state ----------------------------------------
__device__ u32 g_h0p[2][Bn * HPS];                  // ping-pong packed h0
__device__ u32 g_outsp[(size_t)Tn * Bn * HPS];      // packed h1 history
__device__ u32 g_embp[VSn * EMBn];                  // packed embedding
struct PadCnt { unsigned v; unsigned pad[31]; };
__device__ PadCnt g_bcnt[2][NGROUP];                // split barriers: cnt
__device__ volatile unsigned g_bph[2][NGROUP * 32]; // split barriers: phase
__device__ unsigned g_allcnt;
__device__ volatile unsigned g_allphase;

// Arrive: all CTA threads' prior stores ordered by syncthreads, t0 releases.
__device__ __forceinline__ void group_arrive(int b, int g) {
    __syncthreads();
    if (threadIdx.x == 0) {
        __threadfence();
        if (atomicAdd(&g_bcnt[b][g].v, 1u) == GSIZE - 1u) {
            g_bcnt[b][g].v = 0u;
            __threadfence();
            g_bph[b][g * 32] = g_bph[b][g * 32] + 1u;
        }
    }
}

// Wait until phase reaches target (absolute, base-relative computed by caller).
__device__ __forceinline__ void group_wait(int b, int g, unsigned target) {
    if (threadIdx.x == 0) {
        while ((int)(g_bph[b][g * 32] - target) < 0) { }
        __threadfence();
    }
    __syncthreads();
}

__device__ __forceinline__ void grid_sync_all() {
    __threadfence();
    __syncthreads();
    if (threadIdx.x == 0) {
        unsigned ph = g_allphase;
        if (atomicAdd(&g_allcnt, 1u) == GRID - 1u) {
            g_allcnt = 0u;
            __threadfence();
            g_allphase = ph + 1u;
        } else {
            while (g_allphase == ph) { }
        }
    }
    __syncthreads();
}

// -------- fp16 split + mma helpers ---------------------------------------
__device__ __forceinline__ void split2(float x, float y, u32& hi, u32& lo) {
    __half hx = __float2half_rn(x), hy = __float2half_rn(y);
    __half lx = __float2half_rn(x - __half2float(hx));
    __half ly = __float2half_rn(y - __half2float(hy));
    __half2 h = __halves2half2(hx, hy), l = __halves2half2(lx, ly);
    hi = *(u32*)&h; lo = *(u32*)&l;
}

__device__ __forceinline__ int permslot(int kp) {
    int p = kp & 7;
    return (kp & ~7) + ((p < 4) ? 2 * p : 2 * p - 7);
}

__device__ __forceinline__ void mma16816(float c[4],
                                         u32 a0, u32 a1, u32 a2, u32 a3,
                                         u32 b0, u32 b1) {
    asm volatile(
        "mma.sync.aligned.m16n8k16.row.col.f32.f16.f16.f32 "
        "{%0,%1,%2,%3}, {%4,%5,%6,%7}, {%8,%9}, {%0,%1,%2,%3};"
        : "+f"(c[0]), "+f"(c[1]), "+f"(c[2]), "+f"(c[3])
        : "r"(a0), "r"(a1), "r"(a2), "r"(a3), "r"(b0), "r"(b1));
}

// One chunk, this warp's k16 block, ALL 4 n-blocks. B fragment = one LDS.128
// {hi0,hi1,lo0,lo1} from the combined plane; 3 split products each.
__device__ __forceinline__ void chunk_mma4c(uint4 u0, uint4 u1,
                                            const u32* __restrict__ Wc,
                                            int bbase, float acc[4][4]) {
    #pragma unroll
    for (int jl = 0; jl < 4; ++jl) {
        uint4 Bq = *(const uint4*)(Wc + bbase + jl * (8 * WSC));
        mma16816(acc[jl], u0.x, u1.x, u0.z, u1.z, Bq.x, Bq.y);  // Ah*Bh
        mma16816(acc[jl], u0.x, u1.x, u0.z, u1.z, Bq.z, Bq.w);  // Ah*Bl
        mma16816(acc[jl], u0.y, u1.y, u0.w, u1.w, Bq.x, Bq.y);  // Al*Bh
    }
}

__device__ __forceinline__ void zero4(float a[4][4]) {
    #pragma unroll
    for (int j = 0; j < 4; ++j)
        #pragma unroll
        for (int r = 0; r < 4; ++r) a[j][r] = 0.f;
}

// K-split reduction + bias + tanh + 2 packed (hi,lo) stores per thread.
// NOTE: no trailing sync — caller provides separation before red reuse.
__device__ __forceinline__ void epilogue_one(const float acc[4][4], float* red,
                                             int wid, int lane, int rbase,
                                             float ba, float bb,
                                             size_t po0, size_t po1,
                                             u32* __restrict__ destp) {
    float* st = red + wid * RS + lane * 17;
    #pragma unroll
    for (int jl = 0; jl < 4; ++jl) {
        st[jl * 4 + 0] = acc[jl][0]; st[jl * 4 + 1] = acc[jl][1];
        st[jl * 4 + 2] = acc[jl][2]; st[jl * 4 + 3] = acc[jl][3];
    }
    __syncthreads();
    float s00 = 0.f, s01 = 0.f, s10 = 0.f, s11 = 0.f;
    #pragma unroll
    for (int k = 0; k < 4; ++k) {
        const float* q = red + rbase + k * (2 * RS);
        s00 += q[0]; s01 += q[1]; s10 += q[2]; s11 += q[3];
    }
    u32 hi, lo;
    split2(tanhf(s00 + ba), tanhf(s01 + bb), hi, lo);
    *(uint2*)(destp + po0) = make_uint2(hi, lo);
    split2(tanhf(s10 + ba), tanhf(s11 + bb), hi, lo);
    *(uint2*)(destp + po1) = make_uint2(hi, lo);
}

extern __shared__ u32 smem_u[];

__global__ void __launch_bounds__(BLOCKT, 1) rnn_persistent_kernel(
    const int*   __restrict__ x,
    const float* __restrict__ emb,
    const float* __restrict__ W_ih0, const float* __restrict__ b_ih0,
    const float* __restrict__ W_hh0, const float* __restrict__ b_hh0,
    const float* __restrict__ W_ih1, const float* __restrict__ b_ih1,
    const float* __restrict__ W_hh1, const float* __restrict__ b_hh1,
    const float* __restrict__ W_fc,  const float* __restrict__ b_fc,
    float* __restrict__ out)
{
    u32*   Wc  = smem_u;                       // [32 cols][WSC] combined hi/lo
    float* red = (float*)(smem_u + 32 * WSC);  // 5120 floats scratch

    const int tid  = threadIdx.x;
    const int cta  = blockIdx.x;
    const int grp  = cta >> 4;
    const int row0 = grp * 32;
    const int col0 = (cta & 15) * 32;

    // ---- weight slice -> SMEM combined (hi,hi,lo,lo) per slot, permuted ---
    {
        const int c  = tid & 31;
        const int pp = tid >> 5;               // 0..7
        for (int pb = 0; pb < 800; pb += 8) {
            int kp = pb + pp;
            int k  = kp * 2;
            const float* src; int kr;
            if      (k < 64)   { src = W_ih0; kr = k; }
            else if (k < 576)  { src = W_hh0; kr = k - 64; }
            else if (k < 1088) { src = W_ih1; kr = k - 576; }
            else               { src = W_hh1; kr = k - 1088; }
            float w0 = src[(size_t)kr * HSn + col0 + c];
            float w1 = src[(size_t)(kr + 1) * HSn + col0 + c];
            u32 hi, lo;
            split2(w0, w1, hi, lo);
            int pos = permslot(kp);
            int s = pos >> 1, r = pos & 1;
            Wc[c * WSC + s * 4 + r]     = hi;
            Wc[c * WSC + s * 4 + r + 2] = lo;
        }
    }

    // ---- packed embedding precompute: CTA i owns vocab row i -------------
    if (tid < 32) {
        float w0 = emb[cta * EMBn + 2 * tid];
        float w1 = emb[cta * EMBn + 2 * tid + 1];
        u32 hi, lo;
        split2(w0, w1, hi, lo);
        int slot = permslot(tid);
        g_embp[cta * EMBn + slot * 2]     = hi;
        g_embp[cta * EMBn + slot * 2 + 1] = lo;
    }
    grid_sync_all();

    // barrier phase bases (replay-safe: phases are monotonic across launches)
    const unsigned base1 = g_bph[0][grp * 32];
    const unsigned base2 = g_bph[1][grp * 32];

    // ---- warp decomposition: wid = mh + 2*ks (8 warps, 4 n-blocks each) --
    const int wid  = tid >> 5;
    const int lane = tid & 31;
    const int mh   = wid & 1;
    const int ks   = wid >> 1;            // 0..3 K-split
    const int g    = lane >> 2;
    const int kt   = lane & 3;

    const int fr0  = row0 + mh * 16 + g;
    const int fr1  = fr0 + 8;
    const int uoff = (ks * 8 + 2 * kt) * 2;
    const int bcolC = g * WSC + (kt + 4 * ks) * 4;

    // epilogue mapping (validated R12 layout)
    const int mh_r = wid & 1;
    const int jg   = wid >> 1;
    const int gr   = lane >> 2, ktr = lane & 3;
    const int er0  = row0 + mh_r * 16 + gr;
    const int ec0  = col0 + jg * 8 + 2 * ktr;
    const size_t po0 = (size_t)er0 * HPS + permslot(ec0 >> 1) * 2;
    const size_t po1 = (size_t)(er0 + 8) * HPS + permslot(ec0 >> 1) * 2;
    const int rbase = mh_r * RS + (gr * 4 + ktr) * 17 + jg * 4;
    const float l0ba = b_ih0[ec0] + b_hh0[ec0];
    const float l0bb = b_ih0[ec0 + 1] + b_hh0[ec0 + 1];
    const float l1ba = b_ih1[ec0] + b_hh1[ec0];
    const float l1bb = b_ih1[ec0 + 1] + b_hh1[ec0 + 1];

    // ===== pre-loop phase: L0(0) = tanh(emb(0) @ Wih0 + b) ===============
    {
        int xi0 = x[fr0 * Tn + 0];
        int xi1 = x[fr1 * Tn + 0];
        uint4 e0 = __ldcg((const uint4*)(g_embp + xi0 * EMBn + uoff));
        uint4 e1 = __ldcg((const uint4*)(g_embp + xi1 * EMBn + uoff));
        float aL0[4][4];
        zero4(aL0);
        chunk_mma4c(e0, e1, Wc, bcolC, aL0);
        epilogue_one(aL0, red, wid, lane, rbase, l0ba, l0bb, po0, po1,
                     g_h0p[0]);
    }
    group_arrive(1, grp);   // BAR2: h0(0) ready (phase base2+1)

    // ===== main loop: one fused phase per step ===========================
    for (int t = 0; t < Tn; ++t) {
        const u32* h0cur = g_h0p[t & 1];
        u32*       h0nxt = g_h0p[(t & 1) ^ 1];
        const u32* h1prv = g_outsp + ((long)t - 1) * (long)(Bn * HPS);
        u32*       h1cur = g_outsp + (size_t)t * (Bn * HPS);

        const u32* h0c0 = h0cur + (size_t)fr0 * HPS + uoff;
        const u32* h0c1 = h0cur + (size_t)fr1 * HPS + uoff;
        const u32* h1p0 = h1prv + (size_t)fr0 * HPS + uoff;
        const u32* h1p1 = h1prv + (size_t)fr1 * HPS + uoff;

        const bool doL0  = (t + 1 < Tn);
        const bool doH1p = (t > 0);

        float aL1[4][4], aL0[4][4];
        zero4(aL1);
        zero4(aL0);

        // ---- wait h1(t-1), then burst the barrier-independent loads ------
        uint4 H10[8], H11[8], E0, E1;
        if (doH1p) {
            group_wait(0, grp, base1 + (unsigned)t);      // BAR1
            #pragma unroll
            for (int i = 0; i < 8; ++i) {
                H10[i] = __ldcg((const uint4*)(h1p0 + i * 64));
                H11[i] = __ldcg((const uint4*)(h1p1 + i * 64));
            }
        }
        if (doL0) {
            int xi0 = x[fr0 * Tn + t + 1];
            int xi1 = x[fr1 * Tn + t + 1];
            E0 = __ldcg((const uint4*)(g_embp + xi0 * EMBn + uoff));
            E1 = __ldcg((const uint4*)(g_embp + xi1 * EMBn + uoff));
        }

        // ---- wait h0(t) (spin overlaps in-flight LDGs), burst h0 ---------
        group_wait(1, grp, base2 + (unsigned)(t + 1));    // BAR2
        uint4 H00[8], H01[8];
        #pragma unroll
        for (int i = 0; i < 8; ++i) {
            H00[i] = __ldcg((const uint4*)(h0c0 + i * 64));
            H01[i] = __ldcg((const uint4*)(h0c1 + i * 64));
        }

        // ---- MMA stream: h1prev first (arrived earliest), emb, then h0 ---
        if (doH1p) {
            #pragma unroll
            for (int i = 0; i < 8; ++i)
                chunk_mma4c(H10[i], H11[i], Wc, bcolC + 1088 + i * 64, aL1);
        }
        if (doL0)
            chunk_mma4c(E0, E1, Wc, bcolC, aL0);
        #pragma unroll
        for (int i = 0; i < 8; ++i) {
            chunk_mma4c(H00[i], H01[i], Wc, bcolC + 576 + i * 64, aL1);
            if (doL0)
                chunk_mma4c(H00[i], H01[i], Wc, bcolC + 64 + i * 64, aL0);
        }

        // ---- epilogues + split arrives -----------------------------------
        epilogue_one(aL1, red, wid, lane, rbase, l1ba, l1bb, po0, po1, h1cur);
        group_arrive(0, grp);                             // BAR1: h1(t) ready
        if (doL0) {
            epilogue_one(aL0, red, wid, lane, rbase, l0ba, l0bb, po0, po1,
                         h0nxt);
            group_arrive(1, grp);                         // BAR2: h0(t+1) ready
        }
    }

    grid_sync_all();

    // ===== final FC via tensor cores: logits = h1 @ W_fc + b_fc ==========
    u32*   Fhi  = smem_u;                      // [64 cols][WS2]
    u32*   Flo  = smem_u + 64 * WS2;
    float* red2 = (float*)(smem_u + 2 * 64 * WS2);   // 8*RS2 floats

    const int jg2   = wid;                     // 0..7 col block of the pass
    const int base2r = (gr * 4 + ktr) * 33 + jg2 * 4;

    for (int pass = 0; pass < 2; ++pass) {
        __syncthreads();
        for (int i = tid; i < 64 * 256; i += BLOCKT) {
            int cc = i & 63;
            int kp = i >> 6;
            float w0 = W_fc[(size_t)(2 * kp) * VSn + pass * 64 + cc];
            float w1 = W_fc[(size_t)(2 * kp + 1) * VSn + pass * 64 + cc];
            u32 hi, lo;
            split2(w0, w1, hi, lo);
            int slot = permslot(kp);
            Fhi[cc * WS2 + slot] = hi;
            Flo[cc * WS2 + slot] = lo;
        }
        __syncthreads();

        const int cfc = pass * 64 + jg2 * 8 + 2 * ktr;
        const float bfa = b_fc[cfc], bfb = b_fc[cfc + 1];

        for (int ti = 0; ti < 32; ++ti) {
            const int m0 = (cta * 32 + ti) * 32;
            const u32* a0p = g_outsp + (size_t)(m0 + mh * 16 + g) * HPS + uoff;
            const u32* a1p = a0p + 8 * HPS;

            uint4 C0[8], C1[8];
            #pragma unroll
            for (int c = 0; c < 8; ++c) {
                C0[c] = __ldcg((const uint4*)(a0p + c * 64));
                C1[c] = __ldcg((const uint4*)(a1p + c * 64));
            }

            float acc[8][4];
            #pragma unroll
            for (int j = 0; j < 8; ++j)
                #pragma unroll
                for (int r = 0; r < 4; ++r) acc[j][r] = 0.f;

            #pragma unroll
            for (int c = 0; c < 8; ++c) {
                #pragma unroll
                for (int jl = 0; jl < 8; ++jl) {
                    int bb_ = (jl * 8 + g) * WS2 + c * 32 + ks * 8 + 2 * kt;
                    uint2 Bh = *(const uint2*)(Fhi + bb_);
                    uint2 Bl = *(const uint2*)(Flo + bb_);
                    mma16816(acc[jl], C0[c].x, C1[c].x, C0[c].z, C1[c].z,
                             Bh.x, Bh.y);
                    mma16816(acc[jl], C0[c].x, C1[c].x, C0[c].z, C1[c].z,
                             Bl.x, Bl.y);
                    mma16816(acc[jl], C0[c].y, C1[c].y, C0[c].w, C1[c].w,
                             Bh.x, Bh.y);
                }
            }

            {
                float* st = red2 + wid * RS2 + lane * 33;
                #pragma unroll
                for (int jl = 0; jl < 8; ++jl) {
                    st[jl * 4 + 0] = acc[jl][0]; st[jl * 4 + 1] = acc[jl][1];
                    st[jl * 4 + 2] = acc[jl][2]; st[jl * 4 + 3] = acc[jl][3];
                }
                __syncthreads();
                #pragma unroll
                for (int mloc = 0; mloc < 2; ++mloc) {
                    float r0 = 0.f, r1 = 0.f, r2 = 0.f, r3 = 0.f;
                    #pragma unroll
                    for (int k = 0; k < 4; ++k) {
                        const float* q = red2 + (mloc + 2 * k) * RS2 + base2r;
                        r0 += q[0]; r1 += q[1]; r2 += q[2]; r3 += q[3];
                    }
                    #pragma unroll
                    for (int rh2 = 0; rh2 < 2; ++rh2) {
                        const int m  = m0 + mloc * 16 + rh2 * 8 + gr;
                        const int tt = m >> 8;
                        const int bb = m & 255;
                        float2 v = rh2 ? make_float2(r2 + bfa, r3 + bfb)
                                       : make_float2(r0 + bfa, r1 + bfb);
                        *(float2*)(out + ((size_t)bb * Tn + tt) * VSn + cfc) = v;
                    }
                }
                __syncthreads();
            }
        }
    }
}

extern "C" void kernel_launch(void* const* d_in, const int* in_sizes, int n_in,
                              void* d_out, int out_size) {
    const int*   x      = (const int*)  d_in[0];
    const float* emb    = (const float*)d_in[1];
    const float* W_ih0  = (const float*)d_in[2];
    const float* b_ih0  = (const float*)d_in[3];
    const float* W_hh0  = (const float*)d_in[4];
    const float* b_hh0  = (const float*)d_in[5];
    const float* W_ih1  = (const float*)d_in[6];
    const float* b_ih1  = (const float*)d_in[7];
    const float* W_hh1  = (const float*)d_in[8];
    const float* b_hh1  = (const float*)d_in[9];
    const float* W_fc   = (const float*)d_in[10];
    const float* b_fc   = (const float*)d_in[11];
    float* out = (float*)d_out;

    cudaFuncSetAttribute(rnn_persistent_kernel,
                         cudaFuncAttributeMaxDynamicSharedMemorySize, SMEM_BYTES);

    rnn_persistent_kernel<<<GRID, BLOCKT, SMEM_BYTES>>>(
        x, emb, W_ih0, b_ih0, W_hh0, b_hh0,
        W_ih1, b_ih1, W_hh1, b_hh1, W_fc, b_fc, out);
}

// round 14
// speedup vs baseline: 1.4646x; 1.4646x over previous
#include <cuda_runtime.h>
#include <cuda_fp16.h>

// Problem sizes
#define Bn   256
#define Tn   512
#define EMBn 64
#define HSn  512
#define VSn  128

// 8 row-groups (32 batch rows) x 16 col-tiles (32 hidden cols) = 128 CTAs
#define GRID   128
#define NGROUP 8
#define GSIZE  16
#define BLOCKT 256           // 8 warps
#define WSC    1616          // combined W plane row stride (u32); 1616%32==16
#define HPS    512           // packed-h row stride in u32 (256 kpairs * 2)
#define RS     544           // recurrence reduction stride (32*17)
#define WS2    264           // FC B plane row stride
#define RS2    1056          // FC reduction stride (32*33)

#define SMEM_U32   (32 * WSC + 5120)      // 56832 u32
#define SMEM_BYTES (SMEM_U32 * 4)         // 227,328 B

typedef unsigned int u32;

// -------- persistent device state ----------------------------------------
__device__ u32 g_h0p[2][Bn * HPS];                  // ping-pong packed h0
__device__ u32 g_outsp[(size_t)Tn * Bn * HPS];      // packed h1 history
__device__ u32 g_embp[VSn * EMBn];                  // packed embedding
struct PadCnt { unsigned v; unsigned pad[31]; };
__device__ PadCnt g_gcnt[NGROUP];
__device__ volatile unsigned g_gphase[NGROUP * 32];
__device__ unsigned g_allcnt;
__device__ volatile unsigned g_allphase;

// R12-proven barrier: all-thread fence -> syncthreads -> t0 arrive/spin.
__device__ __forceinline__ void group_sync(int g) {
    __threadfence();
    __syncthreads();
    if (threadIdx.x == 0) {
        unsigned ph = g_gphase[g * 32];
        if (atomicAdd(&g_gcnt[g].v, 1u) == GSIZE - 1u) {
            g_gcnt[g].v = 0u;
            __threadfence();
            g_gphase[g * 32] = ph + 1u;
        } else {
            while (g_gphase[g * 32] == ph) { }
        }
    }
    __syncthreads();
}

__device__ __forceinline__ void grid_sync_all() {
    __threadfence();
    __syncthreads();
    if (threadIdx.x == 0) {
        unsigned ph = g_allphase;
        if (atomicAdd(&g_allcnt, 1u) == GRID - 1u) {
            g_allcnt = 0u;
            __threadfence();
            g_allphase = ph + 1u;
        } else {
            while (g_allphase == ph) { }
        }
    }
    __syncthreads();
}

// -------- fp16 split + mma helpers ---------------------------------------
__device__ __forceinline__ void split2(float x, float y, u32& hi, u32& lo) {
    __half hx = __float2half_rn(x), hy = __float2half_rn(y);
    __half lx = __float2half_rn(x - __half2float(hx));
    __half ly = __float2half_rn(y - __half2float(hy));
    __half2 h = __halves2half2(hx, hy), l = __halves2half2(lx, ly);
    hi = *(u32*)&h; lo = *(u32*)&l;
}

__device__ __forceinline__ int permslot(int kp) {
    int p = kp & 7;
    return (kp & ~7) + ((p < 4) ? 2 * p : 2 * p - 7);
}

__device__ __forceinline__ void mma16816(float c[4],
                                         u32 a0, u32 a1, u32 a2, u32 a3,
                                         u32 b0, u32 b1) {
    asm volatile(
        "mma.sync.aligned.m16n8k16.row.col.f32.f16.f16.f32 "
        "{%0,%1,%2,%3}, {%4,%5,%6,%7}, {%8,%9}, {%0,%1,%2,%3};"
        : "+f"(c[0]), "+f"(c[1]), "+f"(c[2]), "+f"(c[3])
        : "r"(a0), "r"(a1), "r"(a2), "r"(a3), "r"(b0), "r"(b1));
}

// One chunk, this warp's k16 block, ALL 4 n-blocks. B fragment = single
// conflict-free LDS.128 {hi0,hi1,lo0,lo1} from the combined plane.
__device__ __forceinline__ void chunk_mma4c(uint4 u0, uint4 u1,
                                            const u32* __restrict__ Wc,
                                            int bbase, float acc[4][4]) {
    #pragma unroll
    for (int jl = 0; jl < 4; ++jl) {
        uint4 Bq = *(const uint4*)(Wc + bbase + jl * (8 * WSC));
        mma16816(acc[jl], u0.x, u1.x, u0.z, u1.z, Bq.x, Bq.y);  // Ah*Bh
        mma16816(acc[jl], u0.x, u1.x, u0.z, u1.z, Bq.z, Bq.w);  // Ah*Bl
        mma16816(acc[jl], u0.y, u1.y, u0.w, u1.w, Bq.x, Bq.y);  // Al*Bh
    }
}

__device__ __forceinline__ void zero4(float a[4][4]) {
    #pragma unroll
    for (int j = 0; j < 4; ++j)
        #pragma unroll
        for (int r = 0; r < 4; ++r) a[j][r] = 0.f;
}

// K-split reduction + bias + tanh + 2 packed (hi,lo) stores per thread.
// NOTE: no trailing sync — caller provides separation before red reuse.
__device__ __forceinline__ void epilogue_one(const float acc[4][4], float* red,
                                             int wid, int lane, int rbase,
                                             float ba, float bb,
                                             size_t po0, size_t po1,
                                             u32* __restrict__ destp) {
    float* st = red + wid * RS + lane * 17;
    #pragma unroll
    for (int jl = 0; jl < 4; ++jl) {
        st[jl * 4 + 0] = acc[jl][0]; st[jl * 4 + 1] = acc[jl][1];
        st[jl * 4 + 2] = acc[jl][2]; st[jl * 4 + 3] = acc[jl][3];
    }
    __syncthreads();
    float s00 = 0.f, s01 = 0.f, s10 = 0.f, s11 = 0.f;
    #pragma unroll
    for (int k = 0; k < 4; ++k) {
        const float* q = red + rbase + k * (2 * RS);
        s00 += q[0]; s01 += q[1]; s10 += q[2]; s11 += q[3];
    }
    u32 hi, lo;
    split2(tanhf(s00 + ba), tanhf(s01 + bb), hi, lo);
    *(uint2*)(destp + po0) = make_uint2(hi, lo);
    split2(tanhf(s10 + ba), tanhf(s11 + bb), hi, lo);
    *(uint2*)(destp + po1) = make_uint2(hi, lo);
}

// Fused phase (R12 structure): burst ALL A LDGs, then MMA — ptxas schedules.
template<bool DOL0, bool DOH1P>
__device__ __forceinline__ void phase_mma(
    int xi0, int xi1,
    const u32* __restrict__ h0c0, const u32* __restrict__ h0c1,
    const u32* __restrict__ h1p0, const u32* __restrict__ h1p1,
    const u32* __restrict__ Wc,
    int bcol, int uoff,
    float aL1[4][4], float aL0[4][4])
{
    constexpr int NCH = (DOL0 ? 9 : 8) + (DOH1P ? 8 : 0);
    uint4 A0[NCH], A1[NCH];
    #pragma unroll
    for (int i = 0; i < NCH; ++i) {
        const u32 *p0, *p1;
        if (DOL0 && i == 0) {
            p0 = g_embp + xi0 * EMBn + uoff;
            p1 = g_embp + xi1 * EMBn + uoff;
        } else {
            int base = DOL0 ? i - 1 : i;
            if (base < 8) { p0 = h0c0 + base * 64; p1 = h0c1 + base * 64; }
            else { p0 = h1p0 + (base - 8) * 64; p1 = h1p1 + (base - 8) * 64; }
        }
        A0[i] = __ldcg((const uint4*)p0);
        A1[i] = __ldcg((const uint4*)p1);
    }
    #pragma unroll
    for (int i = 0; i < NCH; ++i) {
        if (DOL0 && i == 0) {
            chunk_mma4c(A0[i], A1[i], Wc, bcol, aL0);               // emb @ Wih0
        } else {
            const int base = DOL0 ? i - 1 : i;
            if (base < 8) {
                chunk_mma4c(A0[i], A1[i], Wc,
                            bcol + (576 + base * 64), aL1);          // h0 @ Wih1
                if (DOL0)
                    chunk_mma4c(A0[i], A1[i], Wc,
                                bcol + (64 + base * 64), aL0);       // h0 @ Whh0
            } else {
                chunk_mma4c(A0[i], A1[i], Wc,
                            bcol + (1088 + (base - 8) * 64), aL1);   // h1p @ Whh1
            }
        }
    }
}

extern __shared__ u32 smem_u[];

__global__ void __launch_bounds__(BLOCKT, 1) rnn_persistent_kernel(
    const int*   __restrict__ x,
    const float* __restrict__ emb,
    const float* __restrict__ W_ih0, const float* __restrict__ b_ih0,
    const float* __restrict__ W_hh0, const float* __restrict__ b_hh0,
    const float* __restrict__ W_ih1, const float* __restrict__ b_ih1,
    const float* __restrict__ W_hh1, const float* __restrict__ b_hh1,
    const float* __restrict__ W_fc,  const float* __restrict__ b_fc,
    float* __restrict__ out)
{
    u32*   Wc  = smem_u;                       // [32 cols][WSC] combined hi/lo
    float* red = (float*)(smem_u + 32 * WSC);  // 5120 floats scratch

    const int tid  = threadIdx.x;
    const int cta  = blockIdx.x;
    const int grp  = cta >> 4;
    const int row0 = grp * 32;
    const int col0 = (cta & 15) * 32;

    // ---- weight slice -> SMEM combined (hi,hi,lo,lo) per slot-pair --------
    {
        const int c  = tid & 31;
        const int pp = tid >> 5;               // 0..7
        for (int pb = 0; pb < 800; pb += 8) {
            int kp = pb + pp;
            int k  = kp * 2;
            const float* src; int kr;
            if      (k < 64)   { src = W_ih0; kr = k; }
            else if (k < 576)  { src = W_hh0; kr = k - 64; }
            else if (k < 1088) { src = W_ih1; kr = k - 576; }
            else               { src = W_hh1; kr = k - 1088; }
            float w0 = src[(size_t)kr * HSn + col0 + c];
            float w1 = src[(size_t)(kr + 1) * HSn + col0 + c];
            u32 hi, lo;
            split2(w0, w1, hi, lo);
            int pos = permslot(kp);
            int s = pos >> 1, r = pos & 1;
            Wc[c * WSC + s * 4 + r]     = hi;
            Wc[c * WSC + s * 4 + r + 2] = lo;
        }
    }

    // ---- packed embedding precompute: CTA i owns vocab row i -------------
    if (tid < 32) {
        float w0 = emb[cta * EMBn + 2 * tid];
        float w1 = emb[cta * EMBn + 2 * tid + 1];
        u32 hi, lo;
        split2(w0, w1, hi, lo);
        int slot = permslot(tid);
        g_embp[cta * EMBn + slot * 2]     = hi;
        g_embp[cta * EMBn + slot * 2 + 1] = lo;
    }
    grid_sync_all();

    // ---- warp decomposition: wid = mh + 2*ks (8 warps, 4 n-blocks each) --
    const int wid  = tid >> 5;
    const int lane = tid & 31;
    const int mh   = wid & 1;
    const int ks   = wid >> 1;            // 0..3 K-split
    const int g    = lane >> 2;
    const int kt   = lane & 3;

    const int fr0  = row0 + mh * 16 + g;
    const int fr1  = fr0 + 8;
    const int uoff = (ks * 8 + 2 * kt) * 2;
    const int bcolC = g * WSC + (kt + 4 * ks) * 4;

    // epilogue mapping (validated R12 layout)
    const int mh_r = wid & 1;
    const int jg   = wid >> 1;
    const int gr   = lane >> 2, ktr = lane & 3;
    const int er0  = row0 + mh_r * 16 + gr;
    const int ec0  = col0 + jg * 8 + 2 * ktr;
    const size_t po0 = (size_t)er0 * HPS + permslot(ec0 >> 1) * 2;
    const size_t po1 = (size_t)(er0 + 8) * HPS + permslot(ec0 >> 1) * 2;
    const int rbase = mh_r * RS + (gr * 4 + ktr) * 17 + jg * 4;
    const float l0ba = b_ih0[ec0] + b_hh0[ec0];
    const float l0bb = b_ih0[ec0 + 1] + b_hh0[ec0 + 1];
    const float l1ba = b_ih1[ec0] + b_hh1[ec0];
    const float l1bb = b_ih1[ec0 + 1] + b_hh1[ec0 + 1];

    // ===== pre-loop phase: L0(0) = tanh(emb(0) @ Wih0 + b) ===============
    {
        int xi0 = x[fr0 * Tn + 0];
        int xi1 = x[fr1 * Tn + 0];
        uint4 e0 = __ldcg((const uint4*)(g_embp + xi0 * EMBn + uoff));
        uint4 e1 = __ldcg((const uint4*)(g_embp + xi1 * EMBn + uoff));
        float aL0[4][4];
        zero4(aL0);
        chunk_mma4c(e0, e1, Wc, bcolC, aL0);
        epilogue_one(aL0, red, wid, lane, rbase, l0ba, l0bb, po0, po1,
                     g_h0p[0]);
    }
    group_sync(grp);

    // ===== main loop: one fused phase per step ===========================
    for (int t = 0; t < Tn; ++t) {
        const u32* h0cur = g_h0p[t & 1];
        u32*       h0nxt = g_h0p[(t & 1) ^ 1];
        const u32* h1prv = g_outsp + ((long)t - 1) * (long)(Bn * HPS);
        u32*       h1cur = g_outsp + (size_t)t * (Bn * HPS);

        const u32* h0c0 = h0cur + (size_t)fr0 * HPS + uoff;
        const u32* h0c1 = h0cur + (size_t)fr1 * HPS + uoff;
        const u32* h1p0 = h1prv + (size_t)fr0 * HPS + uoff;
        const u32* h1p1 = h1prv + (size_t)fr1 * HPS + uoff;

        int xi0 = 0, xi1 = 0;
        if (t + 1 < Tn) {
            xi0 = x[fr0 * Tn + t + 1];
            xi1 = x[fr1 * Tn + t + 1];
        }

        float aL1[4][4], aL0[4][4];
        zero4(aL1);
        zero4(aL0);

        if (t == 0)
            phase_mma<true, false>(xi0, xi1, h0c0, h0c1, h1p0, h1p1,
                                   Wc, bcolC, uoff, aL1, aL0);
        else if (t + 1 < Tn)
            phase_mma<true, true>(xi0, xi1, h0c0, h0c1, h1p0, h1p1,
                                  Wc, bcolC, uoff, aL1, aL0);
        else
            phase_mma<false, true>(xi0, xi1, h0c0, h0c1, h1p0, h1p1,
                                   Wc, bcolC, uoff, aL1, aL0);

        epilogue_one(aL1, red, wid, lane, rbase, l1ba, l1bb, po0, po1, h1cur);
        if (t + 1 < Tn) {
            __syncthreads();   // red reuse
            epilogue_one(aL0, red, wid, lane, rbase, l0ba, l0bb, po0, po1,
                         h0nxt);
        }
        group_sync(grp);       // h1(t), h0(t+1) visible group-wide
    }

    grid_sync_all();

    // ===== final FC via tensor cores: logits = h1 @ W_fc + b_fc ==========
    u32*   Fhi  = smem_u;                      // [64 cols][WS2]
    u32*   Flo  = smem_u + 64 * WS2;
    float* red2 = (float*)(smem_u + 2 * 64 * WS2);   // 8*RS2 floats

    const int jg2   = wid;                     // 0..7 col block of the pass
    const int base2 = (gr * 4 + ktr) * 33 + jg2 * 4;

    for (int pass = 0; pass < 2; ++pass) {
        __syncthreads();
        for (int i = tid; i < 64 * 256; i += BLOCKT) {
            int cc = i & 63;
            int kp = i >> 6;
            float w0 = W_fc[(size_t)(2 * kp) * VSn + pass * 64 + cc];
            float w1 = W_fc[(size_t)(2 * kp + 1) * VSn + pass * 64 + cc];
            u32 hi, lo;
            split2(w0, w1, hi, lo);
            int slot = permslot(kp);
            Fhi[cc * WS2 + slot] = hi;
            Flo[cc * WS2 + slot] = lo;
        }
        __syncthreads();

        const int cfc = pass * 64 + jg2 * 8 + 2 * ktr;
        const float bfa = b_fc[cfc], bfb = b_fc[cfc + 1];

        for (int ti = 0; ti < 32; ++ti) {
            const int m0 = (cta * 32 + ti) * 32;
            const u32* a0p = g_outsp + (size_t)(m0 + mh * 16 + g) * HPS + uoff;
            const u32* a1p = a0p + 8 * HPS;

            uint4 C0[8], C1[8];
            #pragma unroll
            for (int c = 0; c < 8; ++c) {
                C0[c] = __ldcg((const uint4*)(a0p + c * 64));
                C1[c] = __ldcg((const uint4*)(a1p + c * 64));
            }

            float acc[8][4];
            #pragma unroll
            for (int j = 0; j < 8; ++j)
                #pragma unroll
                for (int r = 0; r < 4; ++r) acc[j][r] = 0.f;

            #pragma unroll
            for (int c = 0; c < 8; ++c) {
                #pragma unroll
                for (int jl = 0; jl < 8; ++jl) {
                    int bb_ = (jl * 8 + g) * WS2 + c * 32 + ks * 8 + 2 * kt;
                    uint2 Bh = *(const uint2*)(Fhi + bb_);
                    uint2 Bl = *(const uint2*)(Flo + bb_);
                    mma16816(acc[jl], C0[c].x, C1[c].x, C0[c].z, C1[c].z,
                             Bh.x, Bh.y);
                    mma16816(acc[jl], C0[c].x, C1[c].x, C0[c].z, C1[c].z,
                             Bl.x, Bl.y);
                    mma16816(acc[jl], C0[c].y, C1[c].y, C0[c].w, C1[c].w,
                             Bh.x, Bh.y);
                }
            }

            {
                float* st = red2 + wid * RS2 + lane * 33;
                #pragma unroll
                for (int jl = 0; jl < 8; ++jl) {
                    st[jl * 4 + 0] = acc[jl][0]; st[jl * 4 + 1] = acc[jl][1];
                    st[jl * 4 + 2] = acc[jl][2]; st[jl * 4 + 3] = acc[jl][3];
                }
                __syncthreads();
                #pragma unroll
                for (int mloc = 0; mloc < 2; ++mloc) {
                    float r0 = 0.f, r1 = 0.f, r2 = 0.f, r3 = 0.f;
                    #pragma unroll
                    for (int k = 0; k < 4; ++k) {
                        const float* q = red2 + (mloc + 2 * k) * RS2 + base2;
                        r0 += q[0]; r1 += q[1]; r2 += q[2]; r3 += q[3];
                    }
                    #pragma unroll
                    for (int rh2 = 0; rh2 < 2; ++rh2) {
                        const int m  = m0 + mloc * 16 + rh2 * 8 + gr;
                        const int tt = m >> 8;
                        const int bb = m & 255;
                        float2 v = rh2 ? make_float2(r2 + bfa, r3 + bfb)
                                       : make_float2(r0 + bfa, r1 + bfb);
                        *(float2*)(out + ((size_t)bb * Tn + tt) * VSn + cfc) = v;
                    }
                }
                __syncthreads();
            }
        }
    }
}

extern "C" void kernel_launch(void* const* d_in, const int* in_sizes, int n_in,
                              void* d_out, int out_size) {
    const int*   x      = (const int*)  d_in[0];
    const float* emb    = (const float*)d_in[1];
    const float* W_ih0  = (const float*)d_in[2];
    const float* b_ih0  = (const float*)d_in[3];
    const float* W_hh0  = (const float*)d_in[4];
    const float* b_hh0  = (const float*)d_in[5];
    const float* W_ih1  = (const float*)d_in[6];
    const float* b_ih1  = (const float*)d_in[7];
    const float* W_hh1  = (const float*)d_in[8];
    const float* b_hh1  = (const float*)d_in[9];
    const float* W_fc   = (const float*)d_in[10];
    const float* b_fc   = (const float*)d_in[11];
    float* out = (float*)d_out;

    cudaFuncSetAttribute(rnn_persistent_kernel,
                         cudaFuncAttributeMaxDynamicSharedMemorySize, SMEM_BYTES);

    rnn_persistent_kernel<<<GRID, BLOCKT, SMEM_BYTES>>>(
        x, emb, W_ih0, b_ih0, W_hh0, b_hh0,
        W_ih1, b_ih1, W_hh1, b_hh1, W_fc, b_fc, out);
}

// round 15
// speedup vs baseline: 1.4777x; 1.0089x over previous
#include <cuda_runtime.h>
#include <cuda_fp16.h>

// Problem sizes
#define Bn   256
#define Tn   512
#define EMBn 64
#define HSn  512
#define VSn  128

// 8 row-groups (32 batch rows) x 16 col-tiles (32 hidden cols) = 128 CTAs
#define GRID   128
#define NGROUP 8
#define GSIZE  16
#define BLOCKT 256           // 8 warps
#define WSC    1616          // combined W plane row stride (u32); 1616%32==16
#define HPS    512           // packed-h row stride in u32 (256 kpairs * 2)
#define RS     544           // recurrence reduction stride (32*17)
#define WS2    264           // FC B plane row stride
#define RS2    1056          // FC reduction stride (32*33)

#define SMEM_U32   (32 * WSC + 5120)      // 56832 u32
#define SMEM_BYTES (SMEM_U32 * 4)         // 227,328 B

typedef unsigned int u32;

// -------- persistent device state ----------------------------------------
__device__ u32 g_h0p[2][Bn * HPS];                  // ping-pong packed h0
__device__ u32 g_outsp[(size_t)Tn * Bn * HPS];      // packed h1 history
__device__ u32 g_embp[VSn * EMBn];                  // packed embedding
struct PadCnt { unsigned v; unsigned pad[31]; };
__device__ PadCnt g_gcnt[NGROUP];
__device__ volatile unsigned g_gphase[NGROUP * 32];
__device__ unsigned g_allcnt;
__device__ volatile unsigned g_allphase;

// Barrier with t0-only fence: bar.sync gives intra-CTA visibility (cumulative),
// t0's membar.gl releases it group-wide. (Pattern field-validated in R13.)
__device__ __forceinline__ void group_sync(int g) {
    __syncthreads();
    if (threadIdx.x == 0) {
        __threadfence();
        unsigned ph = g_gphase[g * 32];
        if (atomicAdd(&g_gcnt[g].v, 1u) == GSIZE - 1u) {
            g_gcnt[g].v = 0u;
            __threadfence();
            g_gphase[g * 32] = ph + 1u;
        } else {
            while (g_gphase[g * 32] == ph) { }
            __threadfence();
        }
    }
    __syncthreads();
}

__device__ __forceinline__ void grid_sync_all() {
    __syncthreads();
    if (threadIdx.x == 0) {
        __threadfence();
        unsigned ph = g_allphase;
        if (atomicAdd(&g_allcnt, 1u) == GRID - 1u) {
            g_allcnt = 0u;
            __threadfence();
            g_allphase = ph + 1u;
        } else {
            while (g_allphase == ph) { }
            __threadfence();
        }
    }
    __syncthreads();
}

// -------- fast tanh: 1 - 2/(e^{2x}+1) via ex2/rcp approx (~1e-6 rel) -----
__device__ __forceinline__ float tanh_fast(float x) {
    float e, r;
    float f = x * 2.885390082f;            // 2*log2(e)
    asm("ex2.approx.f32 %0, %1;" : "=f"(e) : "f"(f));
    float d = e + 1.0f;
    asm("rcp.approx.f32 %0, %1;" : "=f"(r) : "f"(d));
    return fmaf(-2.0f, r, 1.0f);
}

// -------- fp16 split + mma helpers ---------------------------------------
__device__ __forceinline__ void split2(float x, float y, u32& hi, u32& lo) {
    __half hx = __float2half_rn(x), hy = __float2half_rn(y);
    __half lx = __float2half_rn(x - __half2float(hx));
    __half ly = __float2half_rn(y - __half2float(hy));
    __half2 h = __halves2half2(hx, hy), l = __halves2half2(lx, ly);
    hi = *(u32*)&h; lo = *(u32*)&l;
}

__device__ __forceinline__ int permslot(int kp) {
    int p = kp & 7;
    return (kp & ~7) + ((p < 4) ? 2 * p : 2 * p - 7);
}

__device__ __forceinline__ void mma16816(float c[4],
                                         u32 a0, u32 a1, u32 a2, u32 a3,
                                         u32 b0, u32 b1) {
    asm volatile(
        "mma.sync.aligned.m16n8k16.row.col.f32.f16.f16.f32 "
        "{%0,%1,%2,%3}, {%4,%5,%6,%7}, {%8,%9}, {%0,%1,%2,%3};"
        : "+f"(c[0]), "+f"(c[1]), "+f"(c[2]), "+f"(c[3])
        : "r"(a0), "r"(a1), "r"(a2), "r"(a3), "r"(b0), "r"(b1));
}

// One chunk, this warp's k16 block, ALL 4 n-blocks. B fragment = single
// conflict-free LDS.128 {hi0,hi1,lo0,lo1} from the combined plane.
__device__ __forceinline__ void chunk_mma4c(uint4 u0, uint4 u1,
                                            const u32* __restrict__ Wc,
                                            int bbase, float acc[4][4]) {
    #pragma unroll
    for (int jl = 0; jl < 4; ++jl) {
        uint4 Bq = *(const uint4*)(Wc + bbase + jl * (8 * WSC));
        mma16816(acc[jl], u0.x, u1.x, u0.z, u1.z, Bq.x, Bq.y);  // Ah*Bh
        mma16816(acc[jl], u0.x, u1.x, u0.z, u1.z, Bq.z, Bq.w);  // Ah*Bl
        mma16816(acc[jl], u0.y, u1.y, u0.w, u1.w, Bq.x, Bq.y);  // Al*Bh
    }
}

__device__ __forceinline__ void zero4(float a[4][4]) {
    #pragma unroll
    for (int j = 0; j < 4; ++j)
        #pragma unroll
        for (int r = 0; r < 4; ++r) a[j][r] = 0.f;
}

// K-split reduction + bias + tanh + 2 packed (hi,lo) stores per thread.
// NOTE: no trailing sync — caller provides separation before red reuse.
__device__ __forceinline__ void epilogue_one(const float acc[4][4], float* red,
                                             int wid, int lane, int rbase,
                                             float ba, float bb,
                                             size_t po0, size_t po1,
                                             u32* __restrict__ destp) {
    float* st = red + wid * RS + lane * 17;
    #pragma unroll
    for (int jl = 0; jl < 4; ++jl) {
        st[jl * 4 + 0] = acc[jl][0]; st[jl * 4 + 1] = acc[jl][1];
        st[jl * 4 + 2] = acc[jl][2]; st[jl * 4 + 3] = acc[jl][3];
    }
    __syncthreads();
    float s00 = 0.f, s01 = 0.f, s10 = 0.f, s11 = 0.f;
    #pragma unroll
    for (int k = 0; k < 4; ++k) {
        const float* q = red + rbase + k * (2 * RS);
        s00 += q[0]; s01 += q[1]; s10 += q[2]; s11 += q[3];
    }
    u32 hi, lo;
    split2(tanh_fast(s00 + ba), tanh_fast(s01 + bb), hi, lo);
    *(uint2*)(destp + po0) = make_uint2(hi, lo);
    split2(tanh_fast(s10 + ba), tanh_fast(s11 + bb), hi, lo);
    *(uint2*)(destp + po1) = make_uint2(hi, lo);
}

// Fused phase (R12 structure): burst ALL A LDGs, then MMA — ptxas schedules.
template<bool DOL0, bool DOH1P>
__device__ __forceinline__ void phase_mma(
    int xi0, int xi1,
    const u32* __restrict__ h0c0, const u32* __restrict__ h0c1,
    const u32* __restrict__ h1p0, const u32* __restrict__ h1p1,
    const u32* __restrict__ Wc,
    int bcol, int uoff,
    float aL1[4][4], float aL0[4][4])
{
    constexpr int NCH = (DOL0 ? 9 : 8) + (DOH1P ? 8 : 0);
    uint4 A0[NCH], A1[NCH];
    #pragma unroll
    for (int i = 0; i < NCH; ++i) {
        const u32 *p0, *p1;
        if (DOL0 && i == 0) {
            p0 = g_embp + xi0 * EMBn + uoff;
            p1 = g_embp + xi1 * EMBn + uoff;
        } else {
            int base = DOL0 ? i - 1 : i;
            if (base < 8) { p0 = h0c0 + base * 64; p1 = h0c1 + base * 64; }
            else { p0 = h1p0 + (base - 8) * 64; p1 = h1p1 + (base - 8) * 64; }
        }
        A0[i] = __ldcg((const uint4*)p0);
        A1[i] = __ldcg((const uint4*)p1);
    }
    #pragma unroll
    for (int i = 0; i < NCH; ++i) {
        if (DOL0 && i == 0) {
            chunk_mma4c(A0[i], A1[i], Wc, bcol, aL0);               // emb @ Wih0
        } else {
            const int base = DOL0 ? i - 1 : i;
            if (base < 8) {
                chunk_mma4c(A0[i], A1[i], Wc,
                            bcol + (576 + base * 64), aL1);          // h0 @ Wih1
                if (DOL0)
                    chunk_mma4c(A0[i], A1[i], Wc,
                                bcol + (64 + base * 64), aL0);       // h0 @ Whh0
            } else {
                chunk_mma4c(A0[i], A1[i], Wc,
                            bcol + (1088 + (base - 8) * 64), aL1);   // h1p @ Whh1
            }
        }
    }
}

extern __shared__ u32 smem_u[];

__global__ void __launch_bounds__(BLOCKT, 1) rnn_persistent_kernel(
    const int*   __restrict__ x,
    const float* __restrict__ emb,
    const float* __restrict__ W_ih0, const float* __restrict__ b_ih0,
    const float* __restrict__ W_hh0, const float* __restrict__ b_hh0,
    const float* __restrict__ W_ih1, const float* __restrict__ b_ih1,
    const float* __restrict__ W_hh1, const float* __restrict__ b_hh1,
    const float* __restrict__ W_fc,  const float* __restrict__ b_fc,
    float* __restrict__ out)
{
    u32*   Wc  = smem_u;                       // [32 cols][WSC] combined hi/lo
    float* red = (float*)(smem_u + 32 * WSC);  // 5120 floats scratch

    const int tid  = threadIdx.x;
    const int cta  = blockIdx.x;
    const int grp  = cta >> 4;
    const int row0 = grp * 32;
    const int col0 = (cta & 15) * 32;

    // ---- weight slice -> SMEM combined (hi,hi,lo,lo) per slot-pair --------
    {
        const int c  = tid & 31;
        const int pp = tid >> 5;               // 0..7
        for (int pb = 0; pb < 800; pb += 8) {
            int kp = pb + pp;
            int k  = kp * 2;
            const float* src; int kr;
            if      (k < 64)   { src = W_ih0; kr = k; }
            else if (k < 576)  { src = W_hh0; kr = k - 64; }
            else if (k < 1088) { src = W_ih1; kr = k - 576; }
            else               { src = W_hh1; kr = k - 1088; }
            float w0 = src[(size_t)kr * HSn + col0 + c];
            float w1 = src[(size_t)(kr + 1) * HSn + col0 + c];
            u32 hi, lo;
            split2(w0, w1, hi, lo);
            int pos = permslot(kp);
            int s = pos >> 1, r = pos & 1;
            Wc[c * WSC + s * 4 + r]     = hi;
            Wc[c * WSC + s * 4 + r + 2] = lo;
        }
    }

    // ---- packed embedding precompute: CTA i owns vocab row i -------------
    if (tid < 32) {
        float w0 = emb[cta * EMBn + 2 * tid];
        float w1 = emb[cta * EMBn + 2 * tid + 1];
        u32 hi, lo;
        split2(w0, w1, hi, lo);
        int slot = permslot(tid);
        g_embp[cta * EMBn + slot * 2]     = hi;
        g_embp[cta * EMBn + slot * 2 + 1] = lo;
    }
    grid_sync_all();

    // ---- warp decomposition: wid = mh + 2*ks (8 warps, 4 n-blocks each) --
    const int wid  = tid >> 5;
    const int lane = tid & 31;
    const int mh   = wid & 1;
    const int ks   = wid >> 1;            // 0..3 K-split
    const int g    = lane >> 2;
    const int kt   = lane & 3;

    const int fr0  = row0 + mh * 16 + g;
    const int fr1  = fr0 + 8;
    const int uoff = (ks * 8 + 2 * kt) * 2;
    const int bcolC = g * WSC + (kt + 4 * ks) * 4;

    // epilogue mapping (validated R12 layout)
    const int mh_r = wid & 1;
    const int jg   = wid >> 1;
    const int gr   = lane >> 2, ktr = lane & 3;
    const int er0  = row0 + mh_r * 16 + gr;
    const int ec0  = col0 + jg * 8 + 2 * ktr;
    const size_t po0 = (size_t)er0 * HPS + permslot(ec0 >> 1) * 2;
    const size_t po1 = (size_t)(er0 + 8) * HPS + permslot(ec0 >> 1) * 2;
    const int rbase = mh_r * RS + (gr * 4 + ktr) * 17 + jg * 4;
    const float l0ba = b_ih0[ec0] + b_hh0[ec0];
    const float l0bb = b_ih0[ec0 + 1] + b_hh0[ec0 + 1];
    const float l1ba = b_ih1[ec0] + b_hh1[ec0];
    const float l1bb = b_ih1[ec0 + 1] + b_hh1[ec0 + 1];

    // ===== pre-loop phase: L0(0) = tanh(emb(0) @ Wih0 + b) ===============
    {
        int xi0 = x[fr0 * Tn + 0];
        int xi1 = x[fr1 * Tn + 0];
        uint4 e0 = __ldcg((const uint4*)(g_embp + xi0 * EMBn + uoff));
        uint4 e1 = __ldcg((const uint4*)(g_embp + xi1 * EMBn + uoff));
        float aL0[4][4];
        zero4(aL0);
        chunk_mma4c(e0, e1, Wc, bcolC, aL0);
        epilogue_one(aL0, red, wid, lane, rbase, l0ba, l0bb, po0, po1,
                     g_h0p[0]);
    }
    group_sync(grp);

    // ===== main loop: one fused phase per step ===========================
    for (int t = 0; t < Tn; ++t) {
        const u32* h0cur = g_h0p[t & 1];
        u32*       h0nxt = g_h0p[(t & 1) ^ 1];
        const u32* h1prv = g_outsp + ((long)t - 1) * (long)(Bn * HPS);
        u32*       h1cur = g_outsp + (size_t)t * (Bn * HPS);

        const u32* h0c0 = h0cur + (size_t)fr0 * HPS + uoff;
        const u32* h0c1 = h0cur + (size_t)fr1 * HPS + uoff;
        const u32* h1p0 = h1prv + (size_t)fr0 * HPS + uoff;
        const u32* h1p1 = h1prv + (size_t)fr1 * HPS + uoff;

        int xi0 = 0, xi1 = 0;
        if (t + 1 < Tn) {
            xi0 = x[fr0 * Tn + t + 1];
            xi1 = x[fr1 * Tn + t + 1];
        }

        float aL1[4][4], aL0[4][4];
        zero4(aL1);
        zero4(aL0);

        if (t == 0)
            phase_mma<true, false>(xi0, xi1, h0c0, h0c1, h1p0, h1p1,
                                   Wc, bcolC, uoff, aL1, aL0);
        else if (t + 1 < Tn)
            phase_mma<true, true>(xi0, xi1, h0c0, h0c1, h1p0, h1p1,
                                  Wc, bcolC, uoff, aL1, aL0);
        else
            phase_mma<false, true>(xi0, xi1, h0c0, h0c1, h1p0, h1p1,
                                   Wc, bcolC, uoff, aL1, aL0);

        epilogue_one(aL1, red, wid, lane, rbase, l1ba, l1bb, po0, po1, h1cur);
        if (t + 1 < Tn) {
            __syncthreads();   // red reuse
            epilogue_one(aL0, red, wid, lane, rbase, l0ba, l0bb, po0, po1,
                         h0nxt);
        }
        group_sync(grp);       // h1(t), h0(t+1) visible group-wide
    }

    grid_sync_all();

    // ===== final FC via tensor cores: logits = h1 @ W_fc + b_fc ==========
    u32*   Fhi  = smem_u;                      // [64 cols][WS2]
    u32*   Flo  = smem_u + 64 * WS2;
    float* red2 = (float*)(smem_u + 2 * 64 * WS2);   // 8*RS2 floats

    const int jg2   = wid;                     // 0..7 col block of the pass
    const int base2 = (gr * 4 + ktr) * 33 + jg2 * 4;

    for (int pass = 0; pass < 2; ++pass) {
        __syncthreads();
        for (int i = tid; i < 64 * 256; i += BLOCKT) {
            int cc = i & 63;
            int kp = i >> 6;
            float w0 = W_fc[(size_t)(2 * kp) * VSn + pass * 64 + cc];
            float w1 = W_fc[(size_t)(2 * kp + 1) * VSn + pass * 64 + cc];
            u32 hi, lo;
            split2(w0, w1, hi, lo);
            int slot = permslot(kp);
            Fhi[cc * WS2 + slot] = hi;
            Flo[cc * WS2 + slot] = lo;
        }
        __syncthreads();

        const int cfc = pass * 64 + jg2 * 8 + 2 * ktr;
        const float bfa = b_fc[cfc], bfb = b_fc[cfc + 1];

        for (int ti = 0; ti < 32; ++ti) {
            const int m0 = (cta * 32 + ti) * 32;
            const u32* a0p = g_outsp + (size_t)(m0 + mh * 16 + g) * HPS + uoff;
            const u32* a1p = a0p + 8 * HPS;

            uint4 C0[8], C1[8];
            #pragma unroll
            for (int c = 0; c < 8; ++c) {
                C0[c] = __ldcg((const uint4*)(a0p + c * 64));
                C1[c] = __ldcg((const uint4*)(a1p + c * 64));
            }

            float acc[8][4];
            #pragma unroll
            for (int j = 0; j < 8; ++j)
                #pragma unroll
                for (int r = 0; r < 4; ++r) acc[j][r] = 0.f;

            #pragma unroll
            for (int c = 0; c < 8; ++c) {
                #pragma unroll
                for (int jl = 0; jl < 8; ++jl) {
                    int bb_ = (jl * 8 + g) * WS2 + c * 32 + ks * 8 + 2 * kt;
                    uint2 Bh = *(const uint2*)(Fhi + bb_);
                    uint2 Bl = *(const uint2*)(Flo + bb_);
                    mma16816(acc[jl], C0[c].x, C1[c].x, C0[c].z, C1[c].z,
                             Bh.x, Bh.y);
                    mma16816(acc[jl], C0[c].x, C1[c].x, C0[c].z, C1[c].z,
                             Bl.x, Bl.y);
                    mma16816(acc[jl], C0[c].y, C1[c].y, C0[c].w, C1[c].w,
                             Bh.x, Bh.y);
                }
            }

            {
                float* st = red2 + wid * RS2 + lane * 33;
                #pragma unroll
                for (int jl = 0; jl < 8; ++jl) {
                    st[jl * 4 + 0] = acc[jl][0]; st[jl * 4 + 1] = acc[jl][1];
                    st[jl * 4 + 2] = acc[jl][2]; st[jl * 4 + 3] = acc[jl][3];
                }
                __syncthreads();
                #pragma unroll
                for (int mloc = 0; mloc < 2; ++mloc) {
                    float r0 = 0.f, r1 = 0.f, r2 = 0.f, r3 = 0.f;
                    #pragma unroll
                    for (int k = 0; k < 4; ++k) {
                        const float* q = red2 + (mloc + 2 * k) * RS2 + base2;
                        r0 += q[0]; r1 += q[1]; r2 += q[2]; r3 += q[3];
                    }
                    #pragma unroll
                    for (int rh2 = 0; rh2 < 2; ++rh2) {
                        const int m  = m0 + mloc * 16 + rh2 * 8 + gr;
                        const int tt = m >> 8;
                        const int bb = m & 255;
                        float2 v = rh2 ? make_float2(r2 + bfa, r3 + bfb)
                                       : make_float2(r0 + bfa, r1 + bfb);
                        *(float2*)(out + ((size_t)bb * Tn + tt) * VSn + cfc) = v;
                    }
                }
                __syncthreads();
            }
        }
    }
}

extern "C" void kernel_launch(void* const* d_in, const int* in_sizes, int n_in,
                              void* d_out, int out_size) {
    const int*   x      = (const int*)  d_in[0];
    const float* emb    = (const float*)d_in[1];
    const float* W_ih0  = (const float*)d_in[2];
    const float* b_ih0  = (const float*)d_in[3];
    const float* W_hh0  = (const float*)d_in[4];
    const float* b_hh0  = (const float*)d_in[5];
    const float* W_ih1  = (const float*)d_in[6];
    const float* b_ih1  = (const float*)d_in[7];
    const float* W_hh1  = (const float*)d_in[8];
    const float* b_hh1  = (const float*)d_in[9];
    const float* W_fc   = (const float*)d_in[10];
    const float* b_fc   = (const float*)d_in[11];
    float* out = (float*)d_out;

    cudaFuncSetAttribute(rnn_persistent_kernel,
                         cudaFuncAttributeMaxDynamicSharedMemorySize, SMEM_BYTES);

    rnn_persistent_kernel<<<GRID, BLOCKT, SMEM_BYTES>>>(
        x, emb, W_ih0, b_ih0, W_hh0, b_hh0,
        W_ih1, b_ih1, W_hh1, b_hh1, W_fc, b_fc, out);
}